// round 3
// baseline (speedup 1.0000x reference)
#include <cuda_runtime.h>
#include <math.h>

// Problem dims (fixed)
#define N_TOK  4096          // B*T
#define DIM    512           // D
#define N_EXP  16            // E
#define TOPK   4             // K
#define HID    2048          // H
#define N_PAIR (N_TOK*TOPK)  // 16384

// ---------------- scratch (device globals; no runtime alloc) ----------------
__device__ float g_h  [N_TOK * DIM];                 // projected tokens (per view)
__device__ float g_r  [N_TOK * DIM];                 // routed tokens
__device__ float g_hid [(size_t)N_PAIR * HID];       // expert hidden (128 MB)
__device__ float g_slot[(size_t)N_PAIR * DIM];       // gated expert output per pair
__device__ int   g_pair_token[N_PAIR];
__device__ float g_pair_gate [N_PAIR];
__device__ int   g_pairpos   [N_TOK * TOPK];         // (token,slot) -> pair position
__device__ int   g_tok_eidx  [N_TOK * TOPK];
__device__ float g_tok_gate  [N_TOK * TOPK];
__device__ int   g_counts [N_EXP];
__device__ int   g_offsets[N_EXP + 1];
__device__ int   g_cursor [N_EXP];

__device__ __forceinline__ float gelu_exact(float x) {
    return 0.5f * x * (1.0f + erff(x * 0.70710678118654752440f));
}

// ---------------- generic SGEMM: C[M,N] = A[M,K] @ B[K,N] (+bias) -----------
// BM=128, BN=64, BK=16, 256 threads, 8x4 per-thread microtile.
template<bool HAS_BIAS>
__global__ __launch_bounds__(256) void sgemm_kernel(
    const float* __restrict__ A, const float* __restrict__ B,
    const float* __restrict__ bias, float* __restrict__ C,
    int M, int N, int K)
{
    __shared__ float As[16][128];
    __shared__ float Bs[16][64];
    const int tid = threadIdx.x;
    const int ty = tid >> 4, tx = tid & 15;
    const int m0 = blockIdx.y * 128;
    const int n0 = blockIdx.x * 64;

    const int la_m = tid >> 1;            // 0..127
    const int la_k = (tid & 1) << 3;      // 0 or 8
    const int lb_k = tid >> 4;            // 0..15
    const int lb_n = (tid & 15) << 2;     // 0..60

    const bool a_valid = (m0 + la_m) < M;
    const float* Arow = A + (size_t)(m0 + la_m) * K + la_k;
    const float* Bptr = B + (size_t)lb_k * N + n0 + lb_n;

    float acc[8][4];
#pragma unroll
    for (int i = 0; i < 8; i++)
#pragma unroll
        for (int j = 0; j < 4; j++) acc[i][j] = 0.f;

    for (int k0 = 0; k0 < K; k0 += 16) {
        float4 a0 = make_float4(0.f,0.f,0.f,0.f), a1 = a0;
        if (a_valid) {
            a0 = *(const float4*)(Arow + k0);
            a1 = *(const float4*)(Arow + k0 + 4);
        }
        float4 b = *(const float4*)(Bptr + (size_t)k0 * N);
        __syncthreads();
        As[la_k+0][la_m] = a0.x; As[la_k+1][la_m] = a0.y;
        As[la_k+2][la_m] = a0.z; As[la_k+3][la_m] = a0.w;
        As[la_k+4][la_m] = a1.x; As[la_k+5][la_m] = a1.y;
        As[la_k+6][la_m] = a1.z; As[la_k+7][la_m] = a1.w;
        *(float4*)&Bs[lb_k][lb_n] = b;
        __syncthreads();
#pragma unroll
        for (int kk = 0; kk < 16; kk++) {
            float4 av0 = *(const float4*)&As[kk][ty*8];
            float4 av1 = *(const float4*)&As[kk][ty*8+4];
            float4 bv  = *(const float4*)&Bs[kk][tx*4];
            float a[8] = {av0.x,av0.y,av0.z,av0.w,av1.x,av1.y,av1.z,av1.w};
            float bb[4] = {bv.x,bv.y,bv.z,bv.w};
#pragma unroll
            for (int i = 0; i < 8; i++)
#pragma unroll
                for (int j = 0; j < 4; j++)
                    acc[i][j] = fmaf(a[i], bb[j], acc[i][j]);
        }
    }

    float bvals[4] = {0.f,0.f,0.f,0.f};
    if (HAS_BIAS) {
#pragma unroll
        for (int j = 0; j < 4; j++) bvals[j] = bias[n0 + tx*4 + j];
    }
#pragma unroll
    for (int i = 0; i < 8; i++) {
        int row = m0 + ty*8 + i;
        if (row < M) {
            float4 v = make_float4(acc[i][0]+bvals[0], acc[i][1]+bvals[1],
                                   acc[i][2]+bvals[2], acc[i][3]+bvals[3]);
            *(float4*)(C + (size_t)row * N + n0 + tx*4) = v;
        }
    }
}

// ---------------- gate: -cdist to expert keys, top-4 softmax ----------------
__global__ __launch_bounds__(128) void gate_kernel(const float* __restrict__ keys)
{
    const int t = blockIdx.x;
    __shared__ float rs[DIM];
    __shared__ float part[N_EXP][8];
    __shared__ float logit[N_EXP];
    const int tid = threadIdx.x;

    for (int i = tid; i < DIM; i += 128) rs[i] = g_r[(size_t)t * DIM + i];
    __syncthreads();

    const int e = tid >> 3;   // 0..15
    const int l = tid & 7;    // 0..7
    const float* kp = keys + (size_t)e * DIM;
    float s = 0.f;
    for (int i = l; i < DIM; i += 8) {
        float d = rs[i] - kp[i];
        s = fmaf(d, d, s);
    }
    part[e][l] = s;
    __syncthreads();
    if (l == 0) {
        float d2 = 0.f;
#pragma unroll
        for (int j = 0; j < 8; j++) d2 += part[e][j];
        logit[e] = -sqrtf(fmaxf(d2, 0.f));
    }
    __syncthreads();
    if (tid == 0) {
        float lv[N_EXP];
#pragma unroll
        for (int i = 0; i < N_EXP; i++) lv[i] = logit[i];
        int   idx[TOPK];
        float val[TOPK];
        bool used[N_EXP];
#pragma unroll
        for (int i = 0; i < N_EXP; i++) used[i] = false;
        for (int s2 = 0; s2 < TOPK; s2++) {
            int bi = -1; float bv = -1e30f;
            for (int i = 0; i < N_EXP; i++)
                if (!used[i] && lv[i] > bv) { bv = lv[i]; bi = i; }
            used[bi] = true; idx[s2] = bi; val[s2] = bv;
        }
        float mx = val[0];   // descending order, val[0] is max
        float ex[TOPK], se = 0.f;
        for (int s2 = 0; s2 < TOPK; s2++) { ex[s2] = expf(val[s2] - mx); se += ex[s2]; }
        float inv = 1.0f / se;
        for (int s2 = 0; s2 < TOPK; s2++) {
            g_tok_eidx[t*TOPK + s2] = idx[s2];
            g_tok_gate[t*TOPK + s2] = ex[s2] * inv;
            atomicAdd(&g_counts[idx[s2]], 1);
        }
    }
}

__global__ void zero_counts_kernel() {
    if (threadIdx.x < N_EXP) g_counts[threadIdx.x] = 0;
}

__global__ void scan_kernel() {
    if (threadIdx.x == 0) {
        int o = 0;
        for (int e = 0; e < N_EXP; e++) {
            g_offsets[e] = o;
            g_cursor[e]  = o;
            o += g_counts[e];
        }
        g_offsets[N_EXP] = o;
    }
}

__global__ __launch_bounds__(128) void scatter_kernel() {
    int t = blockIdx.x * 128 + threadIdx.x;
    if (t >= N_TOK) return;
    for (int s = 0; s < TOPK; s++) {
        int e = g_tok_eidx[t*TOPK + s];
        int p = atomicAdd(&g_cursor[e], 1);
        g_pair_token[p] = t;
        g_pair_gate[p]  = g_tok_gate[t*TOPK + s];
        g_pairpos[t*TOPK + s] = p;
    }
}

// ---------------- FFN1: hid[p,:] = gelu(h[tok(p)] @ w1[e] + b1[e]) ----------
__global__ __launch_bounds__(256) void ffn1_kernel(
    const float* __restrict__ w1, const float* __restrict__ b1)
{
    const int e   = blockIdx.z;
    const int off = g_offsets[e];
    const int cnt = g_offsets[e+1] - off;
    const int m0  = blockIdx.y * 128;
    if (m0 >= cnt) return;
    const int n0  = blockIdx.x * 64;

    __shared__ float As[16][128];
    __shared__ float Bs[16][64];
    const int tid = threadIdx.x;
    const int ty = tid >> 4, tx = tid & 15;
    const int la_m = tid >> 1;
    const int la_k = (tid & 1) << 3;
    const int lb_k = tid >> 4;
    const int lb_n = (tid & 15) << 2;

    const bool a_valid = (m0 + la_m) < cnt;
    const int token = a_valid ? g_pair_token[off + m0 + la_m] : 0;
    const float* Arow = g_h + (size_t)token * DIM + la_k;
    const float* Bptr = w1 + (size_t)e * DIM * HID + (size_t)lb_k * HID + n0 + lb_n;

    float acc[8][4];
#pragma unroll
    for (int i = 0; i < 8; i++)
#pragma unroll
        for (int j = 0; j < 4; j++) acc[i][j] = 0.f;

    for (int k0 = 0; k0 < DIM; k0 += 16) {
        float4 a0 = make_float4(0.f,0.f,0.f,0.f), a1 = a0;
        if (a_valid) {
            a0 = *(const float4*)(Arow + k0);
            a1 = *(const float4*)(Arow + k0 + 4);
        }
        float4 b = *(const float4*)(Bptr + (size_t)k0 * HID);
        __syncthreads();
        As[la_k+0][la_m] = a0.x; As[la_k+1][la_m] = a0.y;
        As[la_k+2][la_m] = a0.z; As[la_k+3][la_m] = a0.w;
        As[la_k+4][la_m] = a1.x; As[la_k+5][la_m] = a1.y;
        As[la_k+6][la_m] = a1.z; As[la_k+7][la_m] = a1.w;
        *(float4*)&Bs[lb_k][lb_n] = b;
        __syncthreads();
#pragma unroll
        for (int kk = 0; kk < 16; kk++) {
            float4 av0 = *(const float4*)&As[kk][ty*8];
            float4 av1 = *(const float4*)&As[kk][ty*8+4];
            float4 bv  = *(const float4*)&Bs[kk][tx*4];
            float a[8] = {av0.x,av0.y,av0.z,av0.w,av1.x,av1.y,av1.z,av1.w};
            float bb[4] = {bv.x,bv.y,bv.z,bv.w};
#pragma unroll
            for (int i = 0; i < 8; i++)
#pragma unroll
                for (int j = 0; j < 4; j++)
                    acc[i][j] = fmaf(a[i], bb[j], acc[i][j]);
        }
    }

    float bvals[4];
#pragma unroll
    for (int j = 0; j < 4; j++) bvals[j] = b1[(size_t)e * HID + n0 + tx*4 + j];
#pragma unroll
    for (int i = 0; i < 8; i++) {
        int row = m0 + ty*8 + i;
        if (row < cnt) {
            int p = off + row;
            float4 v;
            v.x = gelu_exact(acc[i][0] + bvals[0]);
            v.y = gelu_exact(acc[i][1] + bvals[1]);
            v.z = gelu_exact(acc[i][2] + bvals[2]);
            v.w = gelu_exact(acc[i][3] + bvals[3]);
            *(float4*)(g_hid + (size_t)p * HID + n0 + tx*4) = v;
        }
    }
}

// ---------------- FFN2: slot[p,:] = gate[p] * (hid[p] @ w2[e] + b2[e]) ------
__global__ __launch_bounds__(256) void ffn2_kernel(
    const float* __restrict__ w2, const float* __restrict__ b2)
{
    const int e   = blockIdx.z;
    const int off = g_offsets[e];
    const int cnt = g_offsets[e+1] - off;
    const int m0  = blockIdx.y * 128;
    if (m0 >= cnt) return;
    const int n0  = blockIdx.x * 64;

    __shared__ float As[16][128];
    __shared__ float Bs[16][64];
    const int tid = threadIdx.x;
    const int ty = tid >> 4, tx = tid & 15;
    const int la_m = tid >> 1;
    const int la_k = (tid & 1) << 3;
    const int lb_k = tid >> 4;
    const int lb_n = (tid & 15) << 2;

    const bool a_valid = (m0 + la_m) < cnt;
    const float* Arow = g_hid + (size_t)(off + (a_valid ? (m0 + la_m) : 0)) * HID + la_k;
    const float* Bptr = w2 + (size_t)e * HID * DIM + (size_t)lb_k * DIM + n0 + lb_n;

    float acc[8][4];
#pragma unroll
    for (int i = 0; i < 8; i++)
#pragma unroll
        for (int j = 0; j < 4; j++) acc[i][j] = 0.f;

    for (int k0 = 0; k0 < HID; k0 += 16) {
        float4 a0 = make_float4(0.f,0.f,0.f,0.f), a1 = a0;
        if (a_valid) {
            a0 = *(const float4*)(Arow + k0);
            a1 = *(const float4*)(Arow + k0 + 4);
        }
        float4 b = *(const float4*)(Bptr + (size_t)k0 * DIM);
        __syncthreads();
        As[la_k+0][la_m] = a0.x; As[la_k+1][la_m] = a0.y;
        As[la_k+2][la_m] = a0.z; As[la_k+3][la_m] = a0.w;
        As[la_k+4][la_m] = a1.x; As[la_k+5][la_m] = a1.y;
        As[la_k+6][la_m] = a1.z; As[la_k+7][la_m] = a1.w;
        *(float4*)&Bs[lb_k][lb_n] = b;
        __syncthreads();
#pragma unroll
        for (int kk = 0; kk < 16; kk++) {
            float4 av0 = *(const float4*)&As[kk][ty*8];
            float4 av1 = *(const float4*)&As[kk][ty*8+4];
            float4 bv  = *(const float4*)&Bs[kk][tx*4];
            float a[8] = {av0.x,av0.y,av0.z,av0.w,av1.x,av1.y,av1.z,av1.w};
            float bb[4] = {bv.x,bv.y,bv.z,bv.w};
#pragma unroll
            for (int i = 0; i < 8; i++)
#pragma unroll
                for (int j = 0; j < 4; j++)
                    acc[i][j] = fmaf(a[i], bb[j], acc[i][j]);
        }
    }

    float bvals[4];
#pragma unroll
    for (int j = 0; j < 4; j++) bvals[j] = b2[(size_t)e * DIM + n0 + tx*4 + j];
#pragma unroll
    for (int i = 0; i < 8; i++) {
        int row = m0 + ty*8 + i;
        if (row < cnt) {
            int p = off + row;
            float gt = g_pair_gate[p];
            float4 v;
            v.x = gt * (acc[i][0] + bvals[0]);
            v.y = gt * (acc[i][1] + bvals[1]);
            v.z = gt * (acc[i][2] + bvals[2]);
            v.w = gt * (acc[i][3] + bvals[3]);
            *(float4*)(g_slot + (size_t)p * DIM + n0 + tx*4) = v;
        }
    }
}

// ---------------- combine: fused[t,:] (+)= sum_s slot[pairpos[t,s],:] -------
__global__ __launch_bounds__(256) void combine_kernel(float* __restrict__ out, int accumulate)
{
    int idx = blockIdx.x * 256 + threadIdx.x;   // over N_TOK * (DIM/4)
    if (idx >= N_TOK * (DIM/4)) return;
    int t = idx >> 7;            // DIM/4 = 128 float4 per token
    int d = (idx & 127) << 2;
    float4 acc;
    if (accumulate) acc = *(float4*)(out + (size_t)t * DIM + d);
    else            acc = make_float4(0.f,0.f,0.f,0.f);
#pragma unroll
    for (int s = 0; s < TOPK; s++) {
        int p = g_pairpos[t*TOPK + s];
        float4 v = *(const float4*)(g_slot + (size_t)p * DIM + d);
        acc.x += v.x; acc.y += v.y; acc.z += v.z; acc.w += v.w;
    }
    *(float4*)(out + (size_t)t * DIM + d) = acc;
}

// ---------------- launch --------------------------------------------------
extern "C" void kernel_launch(void* const* d_in, const int* in_sizes, int n_in,
                              void* d_out, int out_size)
{
    const float* view[2]  = {(const float*)d_in[0], (const float*)d_in[1]};
    const float* proj_w   = (const float*)d_in[2];
    const float* proj_b   = (const float*)d_in[3];
    const float* router_w = (const float*)d_in[4];
    const float* keys     = (const float*)d_in[5];
    const float* w1       = (const float*)d_in[6];
    const float* b1       = (const float*)d_in[7];
    const float* w2       = (const float*)d_in[8];
    const float* b2       = (const float*)d_in[9];
    float* out = (float*)d_out;

    float *hP = nullptr, *rP = nullptr;
    cudaGetSymbolAddress((void**)&hP, g_h);
    cudaGetSymbolAddress((void**)&rP, g_r);

    dim3 gproj(DIM/64, N_TOK/128);            // (8, 32)
    dim3 gffn1(HID/64, N_TOK/128, N_EXP);     // (32, 32, 16)
    dim3 gffn2(DIM/64, N_TOK/128, N_EXP);     // (8, 32, 16)

    for (int v = 0; v < 2; v++) {
        // h = x @ proj_w[v] + proj_b[v]
        sgemm_kernel<true><<<gproj, 256>>>(view[v], proj_w + (size_t)v*DIM*DIM,
                                           proj_b + (size_t)v*DIM, hP,
                                           N_TOK, DIM, DIM);
        // r = h @ router_w[v]
        sgemm_kernel<false><<<gproj, 256>>>(hP, router_w + (size_t)v*DIM*DIM,
                                            nullptr, rP, N_TOK, DIM, DIM);
        zero_counts_kernel<<<1, 32>>>();
        gate_kernel<<<N_TOK, 128>>>(keys);
        scan_kernel<<<1, 1>>>();
        scatter_kernel<<<N_TOK/128, 128>>>();
        ffn1_kernel<<<gffn1, 256>>>(w1, b1);
        ffn2_kernel<<<gffn2, 256>>>(w2, b2);
        combine_kernel<<<(N_TOK*(DIM/4) + 255)/256, 256>>>(out, v);
    }
}

// round 5
// speedup vs baseline: 2.0870x; 2.0870x over previous
#include <cuda_runtime.h>
#include <cuda_bf16.h>
#include <math.h>
#include <stdint.h>

#define N_TOK    4096
#define DIM      512
#define N_EXP    16
#define TOPK     4
#define HID      2048
#define PAIR_CAP 18432
#define MAX_TILES 144

// ---------------- device scratch -------------------------------------------
__device__ __nv_bfloat16 g_x_hi [N_TOK * DIM];
__device__ __nv_bfloat16 g_x_lo [N_TOK * DIM];
__device__ __nv_bfloat16 g_h_hi [N_TOK * DIM];
__device__ __nv_bfloat16 g_h_lo [N_TOK * DIM];
__device__ float         g_r    [N_TOK * DIM];
__device__ __nv_bfloat16 g_pw_hi[2 * DIM * DIM];
__device__ __nv_bfloat16 g_pw_lo[2 * DIM * DIM];
__device__ __nv_bfloat16 g_rw_hi[2 * DIM * DIM];
__device__ __nv_bfloat16 g_rw_lo[2 * DIM * DIM];
__device__ __nv_bfloat16 g_w1_hi[N_EXP * DIM * HID];
__device__ __nv_bfloat16 g_w1_lo[N_EXP * DIM * HID];
__device__ __nv_bfloat16 g_w2_hi[N_EXP * HID * DIM];
__device__ __nv_bfloat16 g_w2_lo[N_EXP * HID * DIM];
__device__ __nv_bfloat16 g_ag_hi [PAIR_CAP * DIM];
__device__ __nv_bfloat16 g_ag_lo [PAIR_CAP * DIM];
__device__ __nv_bfloat16 g_hid_hi[(size_t)PAIR_CAP * HID];
__device__ __nv_bfloat16 g_hid_lo[(size_t)PAIR_CAP * HID];
__device__ float g_slot[(size_t)PAIR_CAP * DIM];

__device__ int   g_pair_token[PAIR_CAP];
__device__ float g_pair_gate [PAIR_CAP];
__device__ int   g_pairpos [N_TOK * TOPK];
__device__ int   g_tok_eidx[N_TOK * TOPK];
__device__ float g_tok_gate[N_TOK * TOPK];
__device__ int   g_counts [N_EXP];
__device__ int   g_offsets[N_EXP + 1];
__device__ int   g_cursor [N_EXP];
__device__ int   g_tile_expert[MAX_TILES];
__device__ int   g_tile_m0   [MAX_TILES];
__device__ int   g_total_tiles;

// ---------------- asm helpers (all sm_80-class, safe on sm_103 target) -----
__device__ __forceinline__ uint32_t smem_u32(const void* p) {
    uint32_t a;
    asm("{ .reg .u64 t; cvta.to.shared.u64 t, %1; cvt.u32.u64 %0, t; }" : "=r"(a) : "l"(p));
    return a;
}
__device__ __forceinline__ void cpa16(uint32_t s, const void* g) {
    asm volatile("cp.async.cg.shared.global [%0], [%1], 16;" :: "r"(s), "l"(g));
}
#define CP_COMMIT() asm volatile("cp.async.commit_group;" ::: "memory")
#define CP_WAIT(n)  asm volatile("cp.async.wait_group %0;" :: "n"(n) : "memory")

__device__ __forceinline__ void ldm_x4(uint32_t* r, uint32_t a) {
    asm volatile("ldmatrix.sync.aligned.m8n8.x4.shared.b16 {%0,%1,%2,%3}, [%4];"
        : "=r"(r[0]), "=r"(r[1]), "=r"(r[2]), "=r"(r[3]) : "r"(a));
}
__device__ __forceinline__ void ldm_x4_t(uint32_t* r, uint32_t a) {
    asm volatile("ldmatrix.sync.aligned.m8n8.x4.trans.shared.b16 {%0,%1,%2,%3}, [%4];"
        : "=r"(r[0]), "=r"(r[1]), "=r"(r[2]), "=r"(r[3]) : "r"(a));
}
__device__ __forceinline__ void mma_bf16(float* d, const uint32_t* a, uint32_t b0, uint32_t b1) {
    asm volatile("mma.sync.aligned.m16n8k16.row.col.f32.bf16.bf16.f32 "
        "{%0,%1,%2,%3}, {%4,%5,%6,%7}, {%8,%9}, {%0,%1,%2,%3};"
        : "+f"(d[0]), "+f"(d[1]), "+f"(d[2]), "+f"(d[3])
        : "r"(a[0]), "r"(a[1]), "r"(a[2]), "r"(a[3]), "r"(b0), "r"(b1));
}
__device__ __forceinline__ float gelu_exact(float x) {
    return 0.5f * x * (1.0f + erff(x * 0.70710678118654752440f));
}

// ---------------- HMMA GEMM: D[128,128] tile of A[M,K] @ B[K,N] ------------
// A row-major [M][K] (hi/lo bf16), B row-major [K][N] (hi/lo bf16; ldmatrix.trans).
// bf16x3: acc += Ah*Bh + Ah*Bl + Al*Bh   (fp32 accumulators)
// MODE 0: proj   (+bias        -> g_h hi/lo)
// MODE 1: router (             -> g_r fp32)
// MODE 2: ffn1   (+bias, gelu  -> g_hid hi/lo)
// MODE 3: ffn2   (+bias, *gate -> g_slot fp32)
// SMEM per stage: A hi 10240 + A lo 10240 + B hi 8704 + B lo 8704 = 37888
#define STG   37888
#define SMEM_DYN (3 * STG)

template<int MODE, int KLEN, int NTOT>
__global__ __launch_bounds__(256, 1) void mma_gemm_kernel(
    const __nv_bfloat16* __restrict__ Ah, const __nv_bfloat16* __restrict__ Al,
    const __nv_bfloat16* __restrict__ Bh, const __nv_bfloat16* __restrict__ Bl,
    const float* __restrict__ bias, int zview)
{
    constexpr int NC = KLEN / 32;
    int n0 = blockIdx.x * 128, m0, z;
    if (MODE <= 1) { m0 = blockIdx.y * 128; z = zview; }
    else {
        if ((int)blockIdx.y >= g_total_tiles) return;
        z  = g_tile_expert[blockIdx.y];
        m0 = g_tile_m0[blockIdx.y];
    }
    const __nv_bfloat16* Bhz = Bh + (size_t)z * KLEN * NTOT;
    const __nv_bfloat16* Blz = Bl + (size_t)z * KLEN * NTOT;

    extern __shared__ __align__(16) char smem[];
    uint32_t sb = smem_u32(smem);

    const int tid = threadIdx.x, lane = tid & 31, warp = tid >> 5;
    const int mw = (warp >> 2) * 64, nw = (warp & 3) * 32;
    const int lr = lane & 15, lc = (lane >> 4) << 3;

    // stage loader: 256 threads x 8 cp.async of 16B
    auto load_stage = [&](int s, int c) {
        const int k0 = c * 32;
        const uint32_t base = sb + (uint32_t)s * STG;
#pragma unroll
        for (int i = 0; i < 2; i++) {                 // A: 512 chunks per half
            int ch = tid + i * 256;
            int row = ch >> 2, kc = ch & 3;
            const __nv_bfloat16* ga = Ah + (size_t)(m0 + row) * KLEN + k0 + kc * 8;
            const __nv_bfloat16* gb = Al + (size_t)(m0 + row) * KLEN + k0 + kc * 8;
            cpa16(base +         row * 80 + kc * 16, ga);
            cpa16(base + 10240 + row * 80 + kc * 16, gb);
        }
#pragma unroll
        for (int i = 0; i < 2; i++) {                 // B: 512 chunks per half
            int ch = tid + i * 256;
            int row = ch >> 4, nc = ch & 15;
            const __nv_bfloat16* ga = Bhz + (size_t)(k0 + row) * NTOT + n0 + nc * 8;
            const __nv_bfloat16* gb = Blz + (size_t)(k0 + row) * NTOT + n0 + nc * 8;
            cpa16(base + 20480 + row * 272 + nc * 16, ga);
            cpa16(base + 29184 + row * 272 + nc * 16, gb);
        }
    };

    float acc[4][4][4];
#pragma unroll
    for (int a = 0; a < 4; a++)
#pragma unroll
        for (int b = 0; b < 4; b++)
#pragma unroll
            for (int d = 0; d < 4; d++) acc[a][b][d] = 0.f;

    load_stage(0, 0); CP_COMMIT();
    if (NC > 1) { load_stage(1, 1); CP_COMMIT(); }

    for (int c = 0; c < NC; c++) {
        if (c + 2 < NC) { load_stage((c + 2) % 3, c + 2); CP_COMMIT(); CP_WAIT(2); }
        else if (c + 1 < NC) CP_WAIT(1);
        else CP_WAIT(0);
        __syncthreads();

        const uint32_t base = sb + (uint32_t)(c % 3) * STG;
#pragma unroll
        for (int ks = 0; ks < 2; ks++) {
            uint32_t ah[4][4], al[4][4], bh[2][4], bl[2][4];
#pragma unroll
            for (int ms = 0; ms < 4; ms++) {
                uint32_t ad = base + (uint32_t)((mw + ms * 16 + lr) * 80 + (ks * 16 + lc) * 2);
                ldm_x4(ah[ms], ad);
                ldm_x4(al[ms], ad + 10240);
            }
#pragma unroll
            for (int np = 0; np < 2; np++) {
                uint32_t bd = base + 20480 + (uint32_t)((ks * 16 + lr) * 272 + (nw + np * 16 + lc) * 2);
                ldm_x4_t(bh[np], bd);
                ldm_x4_t(bl[np], bd + 8704);
            }
#pragma unroll
            for (int ms = 0; ms < 4; ms++)
#pragma unroll
                for (int np = 0; np < 2; np++)
#pragma unroll
                    for (int sub = 0; sub < 2; sub++) {
                        int ns = np * 2 + sub;
                        mma_bf16(acc[ms][ns], ah[ms], bh[np][sub*2], bh[np][sub*2+1]);
                        mma_bf16(acc[ms][ns], ah[ms], bl[np][sub*2], bl[np][sub*2+1]);
                        mma_bf16(acc[ms][ns], al[ms], bh[np][sub*2], bh[np][sub*2+1]);
                    }
        }
        __syncthreads();
    }

    // ---- epilogue ----
    const int lrow = lane >> 2, lcol = (lane & 3) * 2;
#pragma unroll
    for (int ms = 0; ms < 4; ms++) {
        int r0 = m0 + mw + ms * 16 + lrow;
        float gt0 = 0.f, gt1 = 0.f;
        if (MODE == 3) { gt0 = g_pair_gate[r0]; gt1 = g_pair_gate[r0 + 8]; }
#pragma unroll
        for (int ns = 0; ns < 4; ns++) {
            int cc = n0 + nw + ns * 8 + lcol;
            float b0 = 0.f, b1 = 0.f;
            if (MODE != 1) {
                b0 = bias[(size_t)z * NTOT + cc];
                b1 = bias[(size_t)z * NTOT + cc + 1];
            }
            float v00 = acc[ms][ns][0] + b0, v01 = acc[ms][ns][1] + b1;
            float v10 = acc[ms][ns][2] + b0, v11 = acc[ms][ns][3] + b1;
            if (MODE == 2) {
                v00 = gelu_exact(v00); v01 = gelu_exact(v01);
                v10 = gelu_exact(v10); v11 = gelu_exact(v11);
            }
            if (MODE == 3) { v00 *= gt0; v01 *= gt0; v10 *= gt1; v11 *= gt1; }
            if (MODE == 1 || MODE == 3) {
                float* OUT = (MODE == 1) ? g_r : g_slot;
                *(float2*)(OUT + (size_t)r0 * NTOT + cc)       = make_float2(v00, v01);
                *(float2*)(OUT + (size_t)(r0 + 8) * NTOT + cc) = make_float2(v10, v11);
            } else {
                __nv_bfloat16* OH = (MODE == 0) ? g_h_hi : g_hid_hi;
                __nv_bfloat16* OL = (MODE == 0) ? g_h_lo : g_hid_lo;
                __nv_bfloat16 h00 = __float2bfloat16(v00), h01 = __float2bfloat16(v01);
                __nv_bfloat16 h10 = __float2bfloat16(v10), h11 = __float2bfloat16(v11);
                *(__nv_bfloat162*)(OH + (size_t)r0 * NTOT + cc)       = __halves2bfloat162(h00, h01);
                *(__nv_bfloat162*)(OH + (size_t)(r0 + 8) * NTOT + cc) = __halves2bfloat162(h10, h11);
                *(__nv_bfloat162*)(OL + (size_t)r0 * NTOT + cc) =
                    __halves2bfloat162(__float2bfloat16(v00 - __bfloat162float(h00)),
                                       __float2bfloat16(v01 - __bfloat162float(h01)));
                *(__nv_bfloat162*)(OL + (size_t)(r0 + 8) * NTOT + cc) =
                    __halves2bfloat162(__float2bfloat16(v10 - __bfloat162float(h10)),
                                       __float2bfloat16(v11 - __bfloat162float(h11)));
            }
        }
    }
}

// ---------------- small kernels ---------------------------------------------
__global__ __launch_bounds__(256) void split_kernel(
    const float* __restrict__ in, __nv_bfloat16* __restrict__ hi,
    __nv_bfloat16* __restrict__ lo, int n)
{
    int i = blockIdx.x * 256 + threadIdx.x;
    if (i < n) {
        float v = in[i];
        __nv_bfloat16 h = __float2bfloat16(v);
        hi[i] = h;
        lo[i] = __float2bfloat16(v - __bfloat162float(h));
    }
}

__global__ __launch_bounds__(128) void gate_kernel(const float* __restrict__ keys)
{
    const int t = blockIdx.x;
    __shared__ float rs[DIM];
    __shared__ float part[N_EXP][8];
    __shared__ float logit[N_EXP];
    const int tid = threadIdx.x;
    for (int i = tid; i < DIM; i += 128) rs[i] = g_r[(size_t)t * DIM + i];
    __syncthreads();
    const int e = tid >> 3, l = tid & 7;
    const float* kp = keys + (size_t)e * DIM;
    float s = 0.f;
    for (int i = l; i < DIM; i += 8) { float d = rs[i] - kp[i]; s = fmaf(d, d, s); }
    part[e][l] = s;
    __syncthreads();
    if (l == 0) {
        float d2 = 0.f;
#pragma unroll
        for (int j = 0; j < 8; j++) d2 += part[e][j];
        logit[e] = -sqrtf(fmaxf(d2, 0.f));
    }
    __syncthreads();
    if (tid == 0) {
        float lv[N_EXP];
#pragma unroll
        for (int i = 0; i < N_EXP; i++) lv[i] = logit[i];
        int idx[TOPK]; float val[TOPK]; bool used[N_EXP];
#pragma unroll
        for (int i = 0; i < N_EXP; i++) used[i] = false;
        for (int s2 = 0; s2 < TOPK; s2++) {
            int bi = -1; float bv = -1e30f;
            for (int i = 0; i < N_EXP; i++)
                if (!used[i] && lv[i] > bv) { bv = lv[i]; bi = i; }
            used[bi] = true; idx[s2] = bi; val[s2] = bv;
        }
        float mx = val[0], ex[TOPK], se = 0.f;
        for (int s2 = 0; s2 < TOPK; s2++) { ex[s2] = expf(val[s2] - mx); se += ex[s2]; }
        float inv = 1.0f / se;
        for (int s2 = 0; s2 < TOPK; s2++) {
            g_tok_eidx[t*TOPK + s2] = idx[s2];
            g_tok_gate[t*TOPK + s2] = ex[s2] * inv;
            atomicAdd(&g_counts[idx[s2]], 1);
        }
    }
}

__global__ __launch_bounds__(256) void reset_kernel() {
    int i = blockIdx.x * 256 + threadIdx.x;
    if (i < PAIR_CAP) { g_pair_token[i] = -1; g_pair_gate[i] = 0.f; }
    if (i < N_EXP) g_counts[i] = 0;
}

__global__ void scan_kernel() {
    if (threadIdx.x == 0) {
        int o = 0, nt = 0;
        for (int e = 0; e < N_EXP; e++) {
            g_offsets[e] = o; g_cursor[e] = o;
            int tiles = (g_counts[e] + 127) >> 7;
            for (int i = 0; i < tiles; i++) { g_tile_expert[nt] = e; g_tile_m0[nt] = o + (i << 7); nt++; }
            o += tiles << 7;
        }
        g_offsets[N_EXP] = o;
        g_total_tiles = nt;
    }
}

__global__ __launch_bounds__(128) void scatter_kernel() {
    int t = blockIdx.x * 128 + threadIdx.x;
    if (t >= N_TOK) return;
    for (int s = 0; s < TOPK; s++) {
        int e = g_tok_eidx[t*TOPK + s];
        int p = atomicAdd(&g_cursor[e], 1);
        g_pair_token[p] = t;
        g_pair_gate[p]  = g_tok_gate[t*TOPK + s];
        g_pairpos[t*TOPK + s] = p;
    }
}

__global__ __launch_bounds__(256) void gather_kernel() {
    int idx = blockIdx.x * 256 + threadIdx.x;
    if (idx >= PAIR_CAP * (DIM / 8)) return;
    int p = idx >> 6, c = (idx & 63) << 3;
    int t = g_pair_token[p];
    uint4 vh = make_uint4(0,0,0,0), vl = vh;
    if (t >= 0) {
        vh = *(const uint4*)(g_h_hi + (size_t)t * DIM + c);
        vl = *(const uint4*)(g_h_lo + (size_t)t * DIM + c);
    }
    *(uint4*)(g_ag_hi + (size_t)p * DIM + c) = vh;
    *(uint4*)(g_ag_lo + (size_t)p * DIM + c) = vl;
}

__global__ __launch_bounds__(256) void combine_kernel(float* __restrict__ out, int accumulate)
{
    int idx = blockIdx.x * 256 + threadIdx.x;
    if (idx >= N_TOK * (DIM/4)) return;
    int t = idx >> 7, d = (idx & 127) << 2;
    float4 acc;
    if (accumulate) acc = *(float4*)(out + (size_t)t * DIM + d);
    else            acc = make_float4(0.f, 0.f, 0.f, 0.f);
#pragma unroll
    for (int s = 0; s < TOPK; s++) {
        int p = g_pairpos[t*TOPK + s];
        float4 v = *(const float4*)(g_slot + (size_t)p * DIM + d);
        acc.x += v.x; acc.y += v.y; acc.z += v.z; acc.w += v.w;
    }
    *(float4*)(out + (size_t)t * DIM + d) = acc;
}

// ---------------- host -----------------------------------------------------
extern "C" void kernel_launch(void* const* d_in, const int* in_sizes, int n_in,
                              void* d_out, int out_size)
{
    const float* view[2]  = {(const float*)d_in[0], (const float*)d_in[1]};
    const float* proj_w   = (const float*)d_in[2];
    const float* proj_b   = (const float*)d_in[3];
    const float* router_w = (const float*)d_in[4];
    const float* keys     = (const float*)d_in[5];
    const float* w1       = (const float*)d_in[6];
    const float* b1       = (const float*)d_in[7];
    const float* w2       = (const float*)d_in[8];
    const float* b2       = (const float*)d_in[9];
    float* out = (float*)d_out;

    void *xhi,*xlo,*hhi,*hlo,*aghi,*aglo,*hidhi,*hidlo;
    void *pwh,*pwl,*rwh,*rwl,*w1h,*w1l,*w2h,*w2l;
    cudaGetSymbolAddress(&xhi, g_x_hi);     cudaGetSymbolAddress(&xlo, g_x_lo);
    cudaGetSymbolAddress(&hhi, g_h_hi);     cudaGetSymbolAddress(&hlo, g_h_lo);
    cudaGetSymbolAddress(&aghi, g_ag_hi);   cudaGetSymbolAddress(&aglo, g_ag_lo);
    cudaGetSymbolAddress(&hidhi, g_hid_hi); cudaGetSymbolAddress(&hidlo, g_hid_lo);
    cudaGetSymbolAddress(&pwh, g_pw_hi);    cudaGetSymbolAddress(&pwl, g_pw_lo);
    cudaGetSymbolAddress(&rwh, g_rw_hi);    cudaGetSymbolAddress(&rwl, g_rw_lo);
    cudaGetSymbolAddress(&w1h, g_w1_hi);    cudaGetSymbolAddress(&w1l, g_w1_lo);
    cudaGetSymbolAddress(&w2h, g_w2_hi);    cudaGetSymbolAddress(&w2l, g_w2_lo);

    cudaFuncSetAttribute(mma_gemm_kernel<0,512,512>,   cudaFuncAttributeMaxDynamicSharedMemorySize, SMEM_DYN);
    cudaFuncSetAttribute(mma_gemm_kernel<1,512,512>,   cudaFuncAttributeMaxDynamicSharedMemorySize, SMEM_DYN);
    cudaFuncSetAttribute(mma_gemm_kernel<2,512,2048>,  cudaFuncAttributeMaxDynamicSharedMemorySize, SMEM_DYN);
    cudaFuncSetAttribute(mma_gemm_kernel<3,2048,512>,  cudaFuncAttributeMaxDynamicSharedMemorySize, SMEM_DYN);

    // split weights to bf16 hi/lo (no transpose needed: B consumed [K][N] via ldmatrix.trans)
    split_kernel<<<(2*DIM*DIM+255)/256, 256>>>(proj_w,   (__nv_bfloat16*)pwh, (__nv_bfloat16*)pwl, 2*DIM*DIM);
    split_kernel<<<(2*DIM*DIM+255)/256, 256>>>(router_w, (__nv_bfloat16*)rwh, (__nv_bfloat16*)rwl, 2*DIM*DIM);
    split_kernel<<<(N_EXP*DIM*HID+255)/256, 256>>>(w1,   (__nv_bfloat16*)w1h, (__nv_bfloat16*)w1l, N_EXP*DIM*HID);
    split_kernel<<<(N_EXP*HID*DIM+255)/256, 256>>>(w2,   (__nv_bfloat16*)w2h, (__nv_bfloat16*)w2l, N_EXP*HID*DIM);

    dim3 gpr(DIM/128, N_TOK/128);          // (4, 32)
    dim3 gf1(HID/128, MAX_TILES);          // (16, 144)
    dim3 gf2(DIM/128, MAX_TILES);          // (4, 144)

    for (int v = 0; v < 2; v++) {
        split_kernel<<<(N_TOK*DIM+255)/256, 256>>>(view[v],
            (__nv_bfloat16*)xhi, (__nv_bfloat16*)xlo, N_TOK*DIM);
        mma_gemm_kernel<0,512,512><<<gpr, 256, SMEM_DYN>>>(
            (const __nv_bfloat16*)xhi, (const __nv_bfloat16*)xlo,
            (const __nv_bfloat16*)pwh, (const __nv_bfloat16*)pwl, proj_b, v);
        mma_gemm_kernel<1,512,512><<<gpr, 256, SMEM_DYN>>>(
            (const __nv_bfloat16*)hhi, (const __nv_bfloat16*)hlo,
            (const __nv_bfloat16*)rwh, (const __nv_bfloat16*)rwl, nullptr, v);
        reset_kernel<<<(PAIR_CAP+255)/256, 256>>>();
        gate_kernel<<<N_TOK, 128>>>(keys);
        scan_kernel<<<1, 1>>>();
        scatter_kernel<<<N_TOK/128, 128>>>();
        gather_kernel<<<(PAIR_CAP*(DIM/8)+255)/256, 256>>>();
        mma_gemm_kernel<2,512,2048><<<gf1, 256, SMEM_DYN>>>(
            (const __nv_bfloat16*)aghi, (const __nv_bfloat16*)aglo,
            (const __nv_bfloat16*)w1h, (const __nv_bfloat16*)w1l, b1, 0);
        mma_gemm_kernel<3,2048,512><<<gf2, 256, SMEM_DYN>>>(
            (const __nv_bfloat16*)hidhi, (const __nv_bfloat16*)hidlo,
            (const __nv_bfloat16*)w2h, (const __nv_bfloat16*)w2l, b2, 0);
        combine_kernel<<<(N_TOK*(DIM/4)+255)/256, 256>>>(out, v);
    }
}

// round 6
// speedup vs baseline: 2.1075x; 1.0098x over previous
#include <cuda_runtime.h>
#include <cuda_bf16.h>
#include <math.h>
#include <stdint.h>

#define N_TOK    4096
#define DIM      512
#define N_EXP    16
#define TOPK     4
#define HID      2048
#define PAIR_CAP 20480          // 16384 pairs + 16 experts * 256 alignment pad
#define MAX_T256 80
#define MAX_T128 160

// ---------------- device scratch -------------------------------------------
__device__ __nv_bfloat16 g_x_hi [N_TOK * DIM];
__device__ __nv_bfloat16 g_x_lo [N_TOK * DIM];
__device__ __nv_bfloat16 g_h_hi [N_TOK * DIM];
__device__ __nv_bfloat16 g_h_lo [N_TOK * DIM];
__device__ float         g_r    [N_TOK * DIM];
__device__ __nv_bfloat16 g_pw_hi[2 * DIM * DIM];
__device__ __nv_bfloat16 g_pw_lo[2 * DIM * DIM];
__device__ __nv_bfloat16 g_rw_hi[2 * DIM * DIM];
__device__ __nv_bfloat16 g_rw_lo[2 * DIM * DIM];
__device__ __nv_bfloat16 g_w1_hi[N_EXP * DIM * HID];
__device__ __nv_bfloat16 g_w1_lo[N_EXP * DIM * HID];
__device__ __nv_bfloat16 g_w2_hi[N_EXP * HID * DIM];
__device__ __nv_bfloat16 g_w2_lo[N_EXP * HID * DIM];
__device__ __nv_bfloat16 g_ag_hi [PAIR_CAP * DIM];
__device__ __nv_bfloat16 g_ag_lo [PAIR_CAP * DIM];
__device__ __nv_bfloat16 g_hid_hi[(size_t)PAIR_CAP * HID];
__device__ __nv_bfloat16 g_hid_lo[(size_t)PAIR_CAP * HID];
__device__ float g_slot[(size_t)PAIR_CAP * DIM];

__device__ int   g_pair_token[PAIR_CAP];
__device__ float g_pair_gate [PAIR_CAP];
__device__ int   g_pairpos [N_TOK * TOPK];
__device__ int   g_tok_eidx[N_TOK * TOPK];
__device__ float g_tok_gate[N_TOK * TOPK];
__device__ int   g_counts [N_EXP];
__device__ int   g_offsets[N_EXP + 1];
__device__ int   g_cursor [N_EXP];
__device__ int   g_t256_e [MAX_T256];
__device__ int   g_t256_m0[MAX_T256];
__device__ int   g_t128_e [MAX_T128];
__device__ int   g_t128_m0[MAX_T128];
__device__ int   g_nt256, g_nt128;

// ---------------- asm helpers ----------------------------------------------
__device__ __forceinline__ uint32_t smem_u32(const void* p) {
    uint32_t a;
    asm("{ .reg .u64 t; cvta.to.shared.u64 t, %1; cvt.u32.u64 %0, t; }" : "=r"(a) : "l"(p));
    return a;
}
__device__ __forceinline__ void cpa16(uint32_t s, const void* g) {
    asm volatile("cp.async.cg.shared.global [%0], [%1], 16;" :: "r"(s), "l"(g));
}
#define CP_COMMIT() asm volatile("cp.async.commit_group;" ::: "memory")
#define CP_WAIT(n)  asm volatile("cp.async.wait_group %0;" :: "n"(n) : "memory")

__device__ __forceinline__ void ldm_x4(uint32_t* r, uint32_t a) {
    asm volatile("ldmatrix.sync.aligned.m8n8.x4.shared.b16 {%0,%1,%2,%3}, [%4];"
        : "=r"(r[0]), "=r"(r[1]), "=r"(r[2]), "=r"(r[3]) : "r"(a));
}
__device__ __forceinline__ void ldm_x4_t(uint32_t* r, uint32_t a) {
    asm volatile("ldmatrix.sync.aligned.m8n8.x4.trans.shared.b16 {%0,%1,%2,%3}, [%4];"
        : "=r"(r[0]), "=r"(r[1]), "=r"(r[2]), "=r"(r[3]) : "r"(a));
}
__device__ __forceinline__ void mma_bf16(float* d, const uint32_t* a, uint32_t b0, uint32_t b1) {
    asm volatile("mma.sync.aligned.m16n8k16.row.col.f32.bf16.bf16.f32 "
        "{%0,%1,%2,%3}, {%4,%5,%6,%7}, {%8,%9}, {%0,%1,%2,%3};"
        : "+f"(d[0]), "+f"(d[1]), "+f"(d[2]), "+f"(d[3])
        : "r"(a[0]), "r"(a[1]), "r"(a[2]), "r"(a[3]), "r"(b0), "r"(b1));
}
__device__ __forceinline__ float gelu_exact(float x) {
    return 0.5f * x * (1.0f + erff(x * 0.70710678118654752440f));
}

// ---------------- HMMA GEMM: D[BM,BN] tile of A[M,K] @ B[K,N] --------------
// A row-major hi/lo bf16, B row-major hi/lo (ldmatrix.trans). bf16x3 split.
// 8 warps, each owns a 64x64 subtile. 3-stage cp.async pipeline.
// MODE 0: proj (+bias -> g_h)  1: router (-> g_r)
// MODE 2: ffn1 (+bias,gelu -> g_hid)  3: ffn2 (+bias,*gate -> g_slot)
template<int MODE, int KLEN, int NTOT, int BM, int BN>
__global__ __launch_bounds__(256, 1) void mma_gemm_kernel(
    const __nv_bfloat16* __restrict__ Ah, const __nv_bfloat16* __restrict__ Al,
    const __nv_bfloat16* __restrict__ Bh, const __nv_bfloat16* __restrict__ Bl,
    const float* __restrict__ bias, int zview)
{
    constexpr int NC     = KLEN / 32;
    constexpr int PB     = BN * 2 + 16;                 // B row pitch bytes
    constexpr int AOFF   = BM * 80;                     // A lo offset
    constexpr int BOFF   = 2 * BM * 80;                 // B hi offset
    constexpr int BOFF2  = BOFF + 32 * PB;              // B lo offset
    constexpr int STG    = 2 * BM * 80 + 64 * PB;       // stage bytes
    constexpr int ACH    = BM * 4;                      // A chunks per half
    constexpr int BCH    = BN * 4;                      // B chunks per half
    constexpr int BROWCH = BN / 8;                      // B chunks per row
    constexpr int WR     = BM / 64;                     // warp rows

    int n0 = blockIdx.x * BN, m0, z;
    if (MODE <= 1) { m0 = blockIdx.y * BM; z = zview; }
    else if (MODE == 2) {
        if ((int)blockIdx.y >= g_nt256) return;
        z = g_t256_e[blockIdx.y]; m0 = g_t256_m0[blockIdx.y];
    } else {
        if ((int)blockIdx.y >= g_nt128) return;
        z = g_t128_e[blockIdx.y]; m0 = g_t128_m0[blockIdx.y];
    }
    const __nv_bfloat16* Bhz = Bh + (size_t)z * KLEN * NTOT;
    const __nv_bfloat16* Blz = Bl + (size_t)z * KLEN * NTOT;

    extern __shared__ __align__(16) char smem[];
    uint32_t sb = smem_u32(smem);

    const int tid = threadIdx.x, lane = tid & 31, warp = tid >> 5;
    const int mw = (warp % WR) * 64, nw = (warp / WR) * 64;
    const int lr = lane & 15, lc = (lane >> 4) << 3;

    auto load_stage = [&](int s, int c) {
        const int k0 = c * 32;
        const uint32_t base = sb + (uint32_t)s * STG;
#pragma unroll
        for (int ch = tid; ch < ACH; ch += 256) {
            int row = ch >> 2, kc = ch & 3;
            cpa16(base +        row * 80 + kc * 16, Ah + (size_t)(m0 + row) * KLEN + k0 + kc * 8);
            cpa16(base + AOFF + row * 80 + kc * 16, Al + (size_t)(m0 + row) * KLEN + k0 + kc * 8);
        }
#pragma unroll
        for (int ch = tid; ch < BCH; ch += 256) {
            int row = ch / BROWCH, nc = ch % BROWCH;
            cpa16(base + BOFF  + row * PB + nc * 16, Bhz + (size_t)(k0 + row) * NTOT + n0 + nc * 8);
            cpa16(base + BOFF2 + row * PB + nc * 16, Blz + (size_t)(k0 + row) * NTOT + n0 + nc * 8);
        }
    };

    float acc[4][8][4];
#pragma unroll
    for (int a = 0; a < 4; a++)
#pragma unroll
        for (int b = 0; b < 8; b++)
#pragma unroll
            for (int d = 0; d < 4; d++) acc[a][b][d] = 0.f;

    load_stage(0, 0); CP_COMMIT();
    if (NC > 1) { load_stage(1, 1); CP_COMMIT(); }

    for (int c = 0; c < NC; c++) {
        if (c + 2 < NC) { load_stage((c + 2) % 3, c + 2); CP_COMMIT(); CP_WAIT(2); }
        else if (c + 1 < NC) CP_WAIT(1);
        else CP_WAIT(0);
        __syncthreads();

        const uint32_t base = sb + (uint32_t)(c % 3) * STG;
#pragma unroll
        for (int ks = 0; ks < 2; ks++) {
            uint32_t ah[4][4], al[4][4];
#pragma unroll
            for (int ms = 0; ms < 4; ms++) {
                uint32_t ad = base + (uint32_t)((mw + ms * 16 + lr) * 80 + (ks * 16 + lc) * 2);
                ldm_x4(ah[ms], ad);
                ldm_x4(al[ms], ad + AOFF);
            }
#pragma unroll
            for (int np = 0; np < 4; np++) {
                uint32_t bh[4], bl[4];
                uint32_t bd = base + BOFF + (uint32_t)((ks * 16 + lr) * PB + (nw + np * 16 + lc) * 2);
                ldm_x4_t(bh, bd);
                ldm_x4_t(bl, bd + 32 * PB);
#pragma unroll
                for (int ms = 0; ms < 4; ms++)
#pragma unroll
                    for (int sub = 0; sub < 2; sub++) {
                        int ns = np * 2 + sub;
                        mma_bf16(acc[ms][ns], ah[ms], bh[sub*2], bh[sub*2+1]);
                        mma_bf16(acc[ms][ns], ah[ms], bl[sub*2], bl[sub*2+1]);
                        mma_bf16(acc[ms][ns], al[ms], bh[sub*2], bh[sub*2+1]);
                    }
            }
        }
        __syncthreads();
    }

    // ---- epilogue ----
    const int lrow = lane >> 2, lcol = (lane & 3) * 2;
#pragma unroll
    for (int ms = 0; ms < 4; ms++) {
        int r0 = m0 + mw + ms * 16 + lrow;
        float gt0 = 0.f, gt1 = 0.f;
        if (MODE == 3) { gt0 = g_pair_gate[r0]; gt1 = g_pair_gate[r0 + 8]; }
#pragma unroll
        for (int ns = 0; ns < 8; ns++) {
            int cc = n0 + nw + ns * 8 + lcol;
            float b0 = 0.f, b1 = 0.f;
            if (MODE != 1) {
                b0 = bias[(size_t)z * NTOT + cc];
                b1 = bias[(size_t)z * NTOT + cc + 1];
            }
            float v00 = acc[ms][ns][0] + b0, v01 = acc[ms][ns][1] + b1;
            float v10 = acc[ms][ns][2] + b0, v11 = acc[ms][ns][3] + b1;
            if (MODE == 2) {
                v00 = gelu_exact(v00); v01 = gelu_exact(v01);
                v10 = gelu_exact(v10); v11 = gelu_exact(v11);
            }
            if (MODE == 3) { v00 *= gt0; v01 *= gt0; v10 *= gt1; v11 *= gt1; }
            if (MODE == 1 || MODE == 3) {
                float* OUT = (MODE == 1) ? g_r : g_slot;
                *(float2*)(OUT + (size_t)r0 * NTOT + cc)       = make_float2(v00, v01);
                *(float2*)(OUT + (size_t)(r0 + 8) * NTOT + cc) = make_float2(v10, v11);
            } else {
                __nv_bfloat16* OH = (MODE == 0) ? g_h_hi : g_hid_hi;
                __nv_bfloat16* OL = (MODE == 0) ? g_h_lo : g_hid_lo;
                __nv_bfloat16 h00 = __float2bfloat16(v00), h01 = __float2bfloat16(v01);
                __nv_bfloat16 h10 = __float2bfloat16(v10), h11 = __float2bfloat16(v11);
                *(__nv_bfloat162*)(OH + (size_t)r0 * NTOT + cc)       = __halves2bfloat162(h00, h01);
                *(__nv_bfloat162*)(OH + (size_t)(r0 + 8) * NTOT + cc) = __halves2bfloat162(h10, h11);
                *(__nv_bfloat162*)(OL + (size_t)r0 * NTOT + cc) =
                    __halves2bfloat162(__float2bfloat16(v00 - __bfloat162float(h00)),
                                       __float2bfloat16(v01 - __bfloat162float(h01)));
                *(__nv_bfloat162*)(OL + (size_t)(r0 + 8) * NTOT + cc) =
                    __halves2bfloat162(__float2bfloat16(v10 - __bfloat162float(h10)),
                                       __float2bfloat16(v11 - __bfloat162float(h11)));
            }
        }
    }
}

// ---------------- small kernels ---------------------------------------------
__global__ __launch_bounds__(256) void split8_kernel(
    const float* __restrict__ in, __nv_bfloat16* __restrict__ hi,
    __nv_bfloat16* __restrict__ lo, int n)
{
    int i = (blockIdx.x * 256 + threadIdx.x) * 8;
    if (i >= n) return;
    float4 a = *(const float4*)(in + i);
    float4 b = *(const float4*)(in + i + 4);
    float v[8] = {a.x, a.y, a.z, a.w, b.x, b.y, b.z, b.w};
    union { __nv_bfloat162 p[4]; uint4 u; } ph, pl;
#pragma unroll
    for (int j = 0; j < 4; j++) {
        __nv_bfloat16 h0 = __float2bfloat16(v[2*j]);
        __nv_bfloat16 h1 = __float2bfloat16(v[2*j+1]);
        ph.p[j] = __halves2bfloat162(h0, h1);
        pl.p[j] = __halves2bfloat162(
            __float2bfloat16(v[2*j]   - __bfloat162float(h0)),
            __float2bfloat16(v[2*j+1] - __bfloat162float(h1)));
    }
    *(uint4*)(hi + i) = ph.u;
    *(uint4*)(lo + i) = pl.u;
}

__global__ __launch_bounds__(128) void gate_kernel(const float* __restrict__ keys)
{
    const int t = blockIdx.x;
    __shared__ float rs[DIM];
    __shared__ float part[N_EXP][8];
    __shared__ float logit[N_EXP];
    const int tid = threadIdx.x;
    for (int i = tid; i < DIM; i += 128) rs[i] = g_r[(size_t)t * DIM + i];
    __syncthreads();
    const int e = tid >> 3, l = tid & 7;
    const float* kp = keys + (size_t)e * DIM;
    float s = 0.f;
    for (int i = l; i < DIM; i += 8) { float d = rs[i] - kp[i]; s = fmaf(d, d, s); }
    part[e][l] = s;
    __syncthreads();
    if (l == 0) {
        float d2 = 0.f;
#pragma unroll
        for (int j = 0; j < 8; j++) d2 += part[e][j];
        logit[e] = -sqrtf(fmaxf(d2, 0.f));
    }
    __syncthreads();
    if (tid == 0) {
        float lv[N_EXP];
#pragma unroll
        for (int i = 0; i < N_EXP; i++) lv[i] = logit[i];
        int idx[TOPK]; float val[TOPK]; bool used[N_EXP];
#pragma unroll
        for (int i = 0; i < N_EXP; i++) used[i] = false;
        for (int s2 = 0; s2 < TOPK; s2++) {
            int bi = -1; float bv = -1e30f;
            for (int i = 0; i < N_EXP; i++)
                if (!used[i] && lv[i] > bv) { bv = lv[i]; bi = i; }
            used[bi] = true; idx[s2] = bi; val[s2] = bv;
        }
        float mx = val[0], ex[TOPK], se = 0.f;
        for (int s2 = 0; s2 < TOPK; s2++) { ex[s2] = expf(val[s2] - mx); se += ex[s2]; }
        float inv = 1.0f / se;
        for (int s2 = 0; s2 < TOPK; s2++) {
            g_tok_eidx[t*TOPK + s2] = idx[s2];
            g_tok_gate[t*TOPK + s2] = ex[s2] * inv;
            atomicAdd(&g_counts[idx[s2]], 1);
        }
    }
}

__global__ __launch_bounds__(256) void reset_kernel() {
    int i = blockIdx.x * 256 + threadIdx.x;
    if (i < PAIR_CAP) { g_pair_token[i] = -1; g_pair_gate[i] = 0.f; }
    if (i < N_EXP) g_counts[i] = 0;
}

__global__ void scan_kernel() {
    if (threadIdx.x == 0) {
        int o = 0, n256 = 0, n128 = 0;
        for (int e = 0; e < N_EXP; e++) {
            g_offsets[e] = o; g_cursor[e] = o;
            int seg = ((g_counts[e] + 255) >> 8) << 8;        // 256-aligned
            for (int i = 0; i < seg / 256; i++) { g_t256_e[n256] = e; g_t256_m0[n256] = o + i * 256; n256++; }
            for (int i = 0; i < seg / 128; i++) { g_t128_e[n128] = e; g_t128_m0[n128] = o + i * 128; n128++; }
            o += seg;
        }
        g_offsets[N_EXP] = o;
        g_nt256 = n256; g_nt128 = n128;
    }
}

__global__ __launch_bounds__(128) void scatter_kernel() {
    int t = blockIdx.x * 128 + threadIdx.x;
    if (t >= N_TOK) return;
    for (int s = 0; s < TOPK; s++) {
        int e = g_tok_eidx[t*TOPK + s];
        int p = atomicAdd(&g_cursor[e], 1);
        g_pair_token[p] = t;
        g_pair_gate[p]  = g_tok_gate[t*TOPK + s];
        g_pairpos[t*TOPK + s] = p;
    }
}

__global__ __launch_bounds__(256) void gather_kernel() {
    int idx = blockIdx.x * 256 + threadIdx.x;
    if (idx >= PAIR_CAP * (DIM / 8)) return;
    int p = idx >> 6, c = (idx & 63) << 3;
    int t = g_pair_token[p];
    uint4 vh = make_uint4(0,0,0,0), vl = vh;
    if (t >= 0) {
        vh = *(const uint4*)(g_h_hi + (size_t)t * DIM + c);
        vl = *(const uint4*)(g_h_lo + (size_t)t * DIM + c);
    }
    *(uint4*)(g_ag_hi + (size_t)p * DIM + c) = vh;
    *(uint4*)(g_ag_lo + (size_t)p * DIM + c) = vl;
}

__global__ __launch_bounds__(256) void combine_kernel(float* __restrict__ out, int accumulate)
{
    int idx = blockIdx.x * 256 + threadIdx.x;
    if (idx >= N_TOK * (DIM/4)) return;
    int t = idx >> 7, d = (idx & 127) << 2;
    float4 acc;
    if (accumulate) acc = *(float4*)(out + (size_t)t * DIM + d);
    else            acc = make_float4(0.f, 0.f, 0.f, 0.f);
#pragma unroll
    for (int s = 0; s < TOPK; s++) {
        int p = g_pairpos[t*TOPK + s];
        float4 v = *(const float4*)(g_slot + (size_t)p * DIM + d);
        acc.x += v.x; acc.y += v.y; acc.z += v.z; acc.w += v.w;
    }
    *(float4*)(out + (size_t)t * DIM + d) = acc;
}

// ---------------- host -----------------------------------------------------
#define STG_OF(BM, BN)  (2 * (BM) * 80 + 64 * ((BN) * 2 + 16))

extern "C" void kernel_launch(void* const* d_in, const int* in_sizes, int n_in,
                              void* d_out, int out_size)
{
    const float* view[2]  = {(const float*)d_in[0], (const float*)d_in[1]};
    const float* proj_w   = (const float*)d_in[2];
    const float* proj_b   = (const float*)d_in[3];
    const float* router_w = (const float*)d_in[4];
    const float* keys     = (const float*)d_in[5];
    const float* w1       = (const float*)d_in[6];
    const float* b1       = (const float*)d_in[7];
    const float* w2       = (const float*)d_in[8];
    const float* b2       = (const float*)d_in[9];
    float* out = (float*)d_out;

    void *xhi,*xlo,*hhi,*hlo,*aghi,*aglo,*hidhi,*hidlo;
    void *pwh,*pwl,*rwh,*rwl,*w1h,*w1l,*w2h,*w2l;
    cudaGetSymbolAddress(&xhi, g_x_hi);     cudaGetSymbolAddress(&xlo, g_x_lo);
    cudaGetSymbolAddress(&hhi, g_h_hi);     cudaGetSymbolAddress(&hlo, g_h_lo);
    cudaGetSymbolAddress(&aghi, g_ag_hi);   cudaGetSymbolAddress(&aglo, g_ag_lo);
    cudaGetSymbolAddress(&hidhi, g_hid_hi); cudaGetSymbolAddress(&hidlo, g_hid_lo);
    cudaGetSymbolAddress(&pwh, g_pw_hi);    cudaGetSymbolAddress(&pwl, g_pw_lo);
    cudaGetSymbolAddress(&rwh, g_rw_hi);    cudaGetSymbolAddress(&rwl, g_rw_lo);
    cudaGetSymbolAddress(&w1h, g_w1_hi);    cudaGetSymbolAddress(&w1l, g_w1_lo);
    cudaGetSymbolAddress(&w2h, g_w2_hi);    cudaGetSymbolAddress(&w2l, g_w2_lo);

    constexpr int SM_PR = 3 * STG_OF(128, 256);   // proj/router/ffn2: 162816
    constexpr int SM_F1 = 3 * STG_OF(256, 128);   // ffn1: 175104
    cudaFuncSetAttribute((const void*)mma_gemm_kernel<0,512,512,128,256>,
                         cudaFuncAttributeMaxDynamicSharedMemorySize, SM_PR);
    cudaFuncSetAttribute((const void*)mma_gemm_kernel<1,512,512,128,256>,
                         cudaFuncAttributeMaxDynamicSharedMemorySize, SM_PR);
    cudaFuncSetAttribute((const void*)mma_gemm_kernel<2,512,2048,256,128>,
                         cudaFuncAttributeMaxDynamicSharedMemorySize, SM_F1);
    cudaFuncSetAttribute((const void*)mma_gemm_kernel<3,2048,512,128,256>,
                         cudaFuncAttributeMaxDynamicSharedMemorySize, SM_PR);

    split8_kernel<<<(2*DIM*DIM/8+255)/256, 256>>>(proj_w,   (__nv_bfloat16*)pwh, (__nv_bfloat16*)pwl, 2*DIM*DIM);
    split8_kernel<<<(2*DIM*DIM/8+255)/256, 256>>>(router_w, (__nv_bfloat16*)rwh, (__nv_bfloat16*)rwl, 2*DIM*DIM);
    split8_kernel<<<(N_EXP*DIM*HID/8+255)/256, 256>>>(w1,   (__nv_bfloat16*)w1h, (__nv_bfloat16*)w1l, N_EXP*DIM*HID);
    split8_kernel<<<(N_EXP*HID*DIM/8+255)/256, 256>>>(w2,   (__nv_bfloat16*)w2h, (__nv_bfloat16*)w2l, N_EXP*HID*DIM);

    dim3 gpr(DIM/256, N_TOK/128);        // (2, 32)
    dim3 gf1(HID/128, MAX_T256);         // (16, 80)
    dim3 gf2(DIM/256, MAX_T128);         // (2, 160)

    for (int v = 0; v < 2; v++) {
        split8_kernel<<<(N_TOK*DIM/8+255)/256, 256>>>(view[v],
            (__nv_bfloat16*)xhi, (__nv_bfloat16*)xlo, N_TOK*DIM);
        mma_gemm_kernel<0,512,512,128,256><<<gpr, 256, SM_PR>>>(
            (const __nv_bfloat16*)xhi, (const __nv_bfloat16*)xlo,
            (const __nv_bfloat16*)pwh, (const __nv_bfloat16*)pwl, proj_b, v);
        mma_gemm_kernel<1,512,512,128,256><<<gpr, 256, SM_PR>>>(
            (const __nv_bfloat16*)hhi, (const __nv_bfloat16*)hlo,
            (const __nv_bfloat16*)rwh, (const __nv_bfloat16*)rwl, nullptr, v);
        reset_kernel<<<(PAIR_CAP+255)/256, 256>>>();
        gate_kernel<<<N_TOK, 128>>>(keys);
        scan_kernel<<<1, 1>>>();
        scatter_kernel<<<N_TOK/128, 128>>>();
        gather_kernel<<<(PAIR_CAP*(DIM/8)+255)/256, 256>>>();
        mma_gemm_kernel<2,512,2048,256,128><<<gf1, 256, SM_F1>>>(
            (const __nv_bfloat16*)aghi, (const __nv_bfloat16*)aglo,
            (const __nv_bfloat16*)w1h, (const __nv_bfloat16*)w1l, b1, 0);
        mma_gemm_kernel<3,2048,512,128,256><<<gf2, 256, SM_PR>>>(
            (const __nv_bfloat16*)hidhi, (const __nv_bfloat16*)hidlo,
            (const __nv_bfloat16*)w2h, (const __nv_bfloat16*)w2l, b2, 0);
        combine_kernel<<<(N_TOK*(DIM/4)+255)/256, 256>>>(out, v);
    }
}

// round 7
// speedup vs baseline: 2.7920x; 1.3248x over previous
#include <cuda_runtime.h>
#include <cuda_fp16.h>
#include <math.h>
#include <stdint.h>

#define N_TOK    4096
#define DIM      512
#define N_EXP    16
#define TOPK     4
#define HID      2048
#define PAIR_CAP 20480          // 16384 pairs + 16 experts * 256 alignment pad
#define MAX_T256 80
#define MAX_T128 160

// ---------------- device scratch -------------------------------------------
__device__ __half g_x_hi [N_TOK * DIM];
__device__ __half g_x_lo [N_TOK * DIM];
__device__ __half g_h_hi [N_TOK * DIM];
__device__ __half g_h_lo [N_TOK * DIM];
__device__ float  g_r    [N_TOK * DIM];
__device__ __half g_pw [2 * DIM * DIM];
__device__ __half g_rw [2 * DIM * DIM];
__device__ __half g_w1 [N_EXP * DIM * HID];
__device__ __half g_w2 [N_EXP * HID * DIM];
__device__ __half g_ag_hi [PAIR_CAP * DIM];
__device__ __half g_ag_lo [PAIR_CAP * DIM];
__device__ __half g_hid_hi[(size_t)PAIR_CAP * HID];
__device__ __half g_hid_lo[(size_t)PAIR_CAP * HID];
__device__ float g_slot[(size_t)PAIR_CAP * DIM];

__device__ int   g_pair_token[PAIR_CAP];
__device__ float g_pair_gate [PAIR_CAP];
__device__ int   g_pairpos [N_TOK * TOPK];
__device__ int   g_tok_eidx[N_TOK * TOPK];
__device__ float g_tok_gate[N_TOK * TOPK];
__device__ int   g_counts [N_EXP];
__device__ int   g_offsets[N_EXP + 1];
__device__ int   g_cursor [N_EXP];
__device__ int   g_t256_e [MAX_T256];
__device__ int   g_t256_m0[MAX_T256];
__device__ int   g_t128_e [MAX_T128];
__device__ int   g_t128_m0[MAX_T128];
__device__ int   g_nt256, g_nt128;

// ---------------- asm helpers ----------------------------------------------
__device__ __forceinline__ uint32_t smem_u32(const void* p) {
    uint32_t a;
    asm("{ .reg .u64 t; cvta.to.shared.u64 t, %1; cvt.u32.u64 %0, t; }" : "=r"(a) : "l"(p));
    return a;
}
__device__ __forceinline__ void cpa16(uint32_t s, const void* g) {
    asm volatile("cp.async.cg.shared.global [%0], [%1], 16;" :: "r"(s), "l"(g));
}
#define CP_COMMIT() asm volatile("cp.async.commit_group;" ::: "memory")
#define CP_WAIT(n)  asm volatile("cp.async.wait_group %0;" :: "n"(n) : "memory")

__device__ __forceinline__ void ldm_x4(uint32_t* r, uint32_t a) {
    asm volatile("ldmatrix.sync.aligned.m8n8.x4.shared.b16 {%0,%1,%2,%3}, [%4];"
        : "=r"(r[0]), "=r"(r[1]), "=r"(r[2]), "=r"(r[3]) : "r"(a));
}
__device__ __forceinline__ void ldm_x4_t(uint32_t* r, uint32_t a) {
    asm volatile("ldmatrix.sync.aligned.m8n8.x4.trans.shared.b16 {%0,%1,%2,%3}, [%4];"
        : "=r"(r[0]), "=r"(r[1]), "=r"(r[2]), "=r"(r[3]) : "r"(a));
}
__device__ __forceinline__ void mma_fp16(float* d, const uint32_t* a, uint32_t b0, uint32_t b1) {
    asm volatile("mma.sync.aligned.m16n8k16.row.col.f32.f16.f16.f32 "
        "{%0,%1,%2,%3}, {%4,%5,%6,%7}, {%8,%9}, {%0,%1,%2,%3};"
        : "+f"(d[0]), "+f"(d[1]), "+f"(d[2]), "+f"(d[3])
        : "r"(a[0]), "r"(a[1]), "r"(a[2]), "r"(a[3]), "r"(b0), "r"(b1));
}
__device__ __forceinline__ float gelu_exact(float x) {
    return 0.5f * x * (1.0f + erff(x * 0.70710678118654752440f));
}

// ---------------- HMMA GEMM: D[BM,BN] tile of A[M,K] @ B[K,N] --------------
// A row-major fp16 hi/lo split, B row-major single fp16 (ldmatrix.trans).
// C = Ah*B + Al*B  (2 MMAs per step, fp32 accum). 8 warps, 64x64 warp tiles.
// MODE 0: proj (+bias -> g_h hi/lo)  1: router (-> g_r)
// MODE 2: ffn1 (+bias,gelu -> g_hid hi/lo)  3: ffn2 (+bias,*gate -> g_slot)
template<int MODE, int KLEN, int NTOT, int BM, int BN>
__global__ __launch_bounds__(256, 1) void mma_gemm_kernel(
    const __half* __restrict__ Ah, const __half* __restrict__ Al,
    const __half* __restrict__ B,
    const float* __restrict__ bias, int zview)
{
    constexpr int NC     = KLEN / 32;
    constexpr int PB     = BN * 2 + 16;                 // B row pitch bytes
    constexpr int AOFF   = BM * 80;                     // A lo offset
    constexpr int BOFF   = 2 * BM * 80;                 // B offset
    constexpr int STG    = 2 * BM * 80 + 32 * PB;       // stage bytes
    constexpr int ACH    = BM * 4;                      // A chunks per half
    constexpr int BCH    = BN * 4;                      // B chunks
    constexpr int BROWCH = BN / 8;
    constexpr int WR     = BM / 64;

    int n0 = blockIdx.x * BN, m0, z;
    if (MODE <= 1) { m0 = blockIdx.y * BM; z = zview; }
    else if (MODE == 2) {
        if ((int)blockIdx.y >= g_nt256) return;
        z = g_t256_e[blockIdx.y]; m0 = g_t256_m0[blockIdx.y];
    } else {
        if ((int)blockIdx.y >= g_nt128) return;
        z = g_t128_e[blockIdx.y]; m0 = g_t128_m0[blockIdx.y];
    }
    const __half* Bz = B + (size_t)z * KLEN * NTOT;

    extern __shared__ __align__(16) char smem[];
    uint32_t sb = smem_u32(smem);

    const int tid = threadIdx.x, lane = tid & 31, warp = tid >> 5;
    const int mw = (warp % WR) * 64, nw = (warp / WR) * 64;
    const int lr = lane & 15, lc = (lane >> 4) << 3;

    auto load_stage = [&](int s, int c) {
        const int k0 = c * 32;
        const uint32_t base = sb + (uint32_t)s * STG;
#pragma unroll
        for (int ch = tid; ch < ACH; ch += 256) {
            int row = ch >> 2, kc = ch & 3;
            cpa16(base +        row * 80 + kc * 16, Ah + (size_t)(m0 + row) * KLEN + k0 + kc * 8);
            cpa16(base + AOFF + row * 80 + kc * 16, Al + (size_t)(m0 + row) * KLEN + k0 + kc * 8);
        }
#pragma unroll
        for (int ch = tid; ch < BCH; ch += 256) {
            int row = ch / BROWCH, nc = ch % BROWCH;
            cpa16(base + BOFF + row * PB + nc * 16, Bz + (size_t)(k0 + row) * NTOT + n0 + nc * 8);
        }
    };

    float acc[4][8][4];
#pragma unroll
    for (int a = 0; a < 4; a++)
#pragma unroll
        for (int b = 0; b < 8; b++)
#pragma unroll
            for (int d = 0; d < 4; d++) acc[a][b][d] = 0.f;

    load_stage(0, 0); CP_COMMIT();
    if (NC > 1) { load_stage(1, 1); CP_COMMIT(); }

    for (int c = 0; c < NC; c++) {
        if (c + 2 < NC) { load_stage((c + 2) % 3, c + 2); CP_COMMIT(); CP_WAIT(2); }
        else if (c + 1 < NC) CP_WAIT(1);
        else CP_WAIT(0);
        __syncthreads();

        const uint32_t base = sb + (uint32_t)(c % 3) * STG;
#pragma unroll
        for (int ks = 0; ks < 2; ks++) {
            uint32_t ah[4][4], al[4][4];
#pragma unroll
            for (int ms = 0; ms < 4; ms++) {
                uint32_t ad = base + (uint32_t)((mw + ms * 16 + lr) * 80 + (ks * 16 + lc) * 2);
                ldm_x4(ah[ms], ad);
                ldm_x4(al[ms], ad + AOFF);
            }
#pragma unroll
            for (int np = 0; np < 4; np++) {
                uint32_t bf[4];
                uint32_t bd = base + BOFF + (uint32_t)((ks * 16 + lr) * PB + (nw + np * 16 + lc) * 2);
                ldm_x4_t(bf, bd);
#pragma unroll
                for (int ms = 0; ms < 4; ms++)
#pragma unroll
                    for (int sub = 0; sub < 2; sub++) {
                        int ns = np * 2 + sub;
                        mma_fp16(acc[ms][ns], ah[ms], bf[sub*2], bf[sub*2+1]);
                        mma_fp16(acc[ms][ns], al[ms], bf[sub*2], bf[sub*2+1]);
                    }
            }
        }
        __syncthreads();
    }

    // ---- epilogue ----
    const int lrow = lane >> 2, lcol = (lane & 3) * 2;
#pragma unroll
    for (int ms = 0; ms < 4; ms++) {
        int r0 = m0 + mw + ms * 16 + lrow;
        float gt0 = 0.f, gt1 = 0.f;
        if (MODE == 3) { gt0 = g_pair_gate[r0]; gt1 = g_pair_gate[r0 + 8]; }
#pragma unroll
        for (int ns = 0; ns < 8; ns++) {
            int cc = n0 + nw + ns * 8 + lcol;
            float b0 = 0.f, b1 = 0.f;
            if (MODE != 1) {
                b0 = bias[(size_t)z * NTOT + cc];
                b1 = bias[(size_t)z * NTOT + cc + 1];
            }
            float v00 = acc[ms][ns][0] + b0, v01 = acc[ms][ns][1] + b1;
            float v10 = acc[ms][ns][2] + b0, v11 = acc[ms][ns][3] + b1;
            if (MODE == 2) {
                v00 = gelu_exact(v00); v01 = gelu_exact(v01);
                v10 = gelu_exact(v10); v11 = gelu_exact(v11);
            }
            if (MODE == 3) { v00 *= gt0; v01 *= gt0; v10 *= gt1; v11 *= gt1; }
            if (MODE == 1 || MODE == 3) {
                float* OUT = (MODE == 1) ? g_r : g_slot;
                *(float2*)(OUT + (size_t)r0 * NTOT + cc)       = make_float2(v00, v01);
                *(float2*)(OUT + (size_t)(r0 + 8) * NTOT + cc) = make_float2(v10, v11);
            } else {
                __half* OH = (MODE == 0) ? g_h_hi : g_hid_hi;
                __half* OL = (MODE == 0) ? g_h_lo : g_hid_lo;
                __half h00 = __float2half(v00), h01 = __float2half(v01);
                __half h10 = __float2half(v10), h11 = __float2half(v11);
                *(__half2*)(OH + (size_t)r0 * NTOT + cc)       = __halves2half2(h00, h01);
                *(__half2*)(OH + (size_t)(r0 + 8) * NTOT + cc) = __halves2half2(h10, h11);
                *(__half2*)(OL + (size_t)r0 * NTOT + cc) =
                    __halves2half2(__float2half(v00 - __half2float(h00)),
                                   __float2half(v01 - __half2float(h01)));
                *(__half2*)(OL + (size_t)(r0 + 8) * NTOT + cc) =
                    __halves2half2(__float2half(v10 - __half2float(h10)),
                                   __float2half(v11 - __half2float(h11)));
            }
        }
    }
}

// ---------------- small kernels ---------------------------------------------
// activations: fp32 -> fp16 hi + fp16 residual lo (8 elts/thread)
__global__ __launch_bounds__(256) void split8_kernel(
    const float* __restrict__ in, __half* __restrict__ hi,
    __half* __restrict__ lo, int n)
{
    int i = (blockIdx.x * 256 + threadIdx.x) * 8;
    if (i >= n) return;
    float4 a = *(const float4*)(in + i);
    float4 b = *(const float4*)(in + i + 4);
    float v[8] = {a.x, a.y, a.z, a.w, b.x, b.y, b.z, b.w};
    union { __half2 p[4]; uint4 u; } ph, pl;
#pragma unroll
    for (int j = 0; j < 4; j++) {
        __half h0 = __float2half(v[2*j]);
        __half h1 = __float2half(v[2*j+1]);
        ph.p[j] = __halves2half2(h0, h1);
        pl.p[j] = __halves2half2(
            __float2half(v[2*j]   - __half2float(h0)),
            __float2half(v[2*j+1] - __half2float(h1)));
    }
    *(uint4*)(hi + i) = ph.u;
    *(uint4*)(lo + i) = pl.u;
}

// weights: fp32 -> single fp16
__global__ __launch_bounds__(256) void conv8_kernel(
    const float* __restrict__ in, __half* __restrict__ out, int n)
{
    int i = (blockIdx.x * 256 + threadIdx.x) * 8;
    if (i >= n) return;
    float4 a = *(const float4*)(in + i);
    float4 b = *(const float4*)(in + i + 4);
    float v[8] = {a.x, a.y, a.z, a.w, b.x, b.y, b.z, b.w};
    union { __half2 p[4]; uint4 u; } ph;
#pragma unroll
    for (int j = 0; j < 4; j++)
        ph.p[j] = __halves2half2(__float2half(v[2*j]), __float2half(v[2*j+1]));
    *(uint4*)(out + i) = ph.u;
}

__global__ __launch_bounds__(128) void gate_kernel(const float* __restrict__ keys)
{
    const int t = blockIdx.x;
    __shared__ float rs[DIM];
    __shared__ float part[N_EXP][8];
    __shared__ float logit[N_EXP];
    const int tid = threadIdx.x;
    for (int i = tid; i < DIM; i += 128) rs[i] = g_r[(size_t)t * DIM + i];
    __syncthreads();
    const int e = tid >> 3, l = tid & 7;
    const float* kp = keys + (size_t)e * DIM;
    float s = 0.f;
    for (int i = l; i < DIM; i += 8) { float d = rs[i] - kp[i]; s = fmaf(d, d, s); }
    part[e][l] = s;
    __syncthreads();
    if (l == 0) {
        float d2 = 0.f;
#pragma unroll
        for (int j = 0; j < 8; j++) d2 += part[e][j];
        logit[e] = -sqrtf(fmaxf(d2, 0.f));
    }
    __syncthreads();
    if (tid == 0) {
        float lv[N_EXP];
#pragma unroll
        for (int i = 0; i < N_EXP; i++) lv[i] = logit[i];
        int idx[TOPK]; float val[TOPK]; bool used[N_EXP];
#pragma unroll
        for (int i = 0; i < N_EXP; i++) used[i] = false;
        for (int s2 = 0; s2 < TOPK; s2++) {
            int bi = -1; float bv = -1e30f;
            for (int i = 0; i < N_EXP; i++)
                if (!used[i] && lv[i] > bv) { bv = lv[i]; bi = i; }
            used[bi] = true; idx[s2] = bi; val[s2] = bv;
        }
        float mx = val[0], ex[TOPK], se = 0.f;
        for (int s2 = 0; s2 < TOPK; s2++) { ex[s2] = expf(val[s2] - mx); se += ex[s2]; }
        float inv = 1.0f / se;
        for (int s2 = 0; s2 < TOPK; s2++) {
            g_tok_eidx[t*TOPK + s2] = idx[s2];
            g_tok_gate[t*TOPK + s2] = ex[s2] * inv;
            atomicAdd(&g_counts[idx[s2]], 1);
        }
    }
}

__global__ __launch_bounds__(256) void reset_kernel() {
    int i = blockIdx.x * 256 + threadIdx.x;
    if (i < PAIR_CAP) { g_pair_token[i] = -1; g_pair_gate[i] = 0.f; }
    if (i < N_EXP) g_counts[i] = 0;
}

__global__ void scan_kernel() {
    if (threadIdx.x == 0) {
        int o = 0, n256 = 0, n128 = 0;
        for (int e = 0; e < N_EXP; e++) {
            g_offsets[e] = o; g_cursor[e] = o;
            int seg = ((g_counts[e] + 255) >> 8) << 8;
            for (int i = 0; i < seg / 256; i++) { g_t256_e[n256] = e; g_t256_m0[n256] = o + i * 256; n256++; }
            for (int i = 0; i < seg / 128; i++) { g_t128_e[n128] = e; g_t128_m0[n128] = o + i * 128; n128++; }
            o += seg;
        }
        g_offsets[N_EXP] = o;
        g_nt256 = n256; g_nt128 = n128;
    }
}

__global__ __launch_bounds__(128) void scatter_kernel() {
    int t = blockIdx.x * 128 + threadIdx.x;
    if (t >= N_TOK) return;
    for (int s = 0; s < TOPK; s++) {
        int e = g_tok_eidx[t*TOPK + s];
        int p = atomicAdd(&g_cursor[e], 1);
        g_pair_token[p] = t;
        g_pair_gate[p]  = g_tok_gate[t*TOPK + s];
        g_pairpos[t*TOPK + s] = p;
    }
}

__global__ __launch_bounds__(256) void gather_kernel() {
    int idx = blockIdx.x * 256 + threadIdx.x;
    if (idx >= PAIR_CAP * (DIM / 8)) return;
    int p = idx >> 6, c = (idx & 63) << 3;
    int t = g_pair_token[p];
    uint4 vh = make_uint4(0,0,0,0), vl = vh;
    if (t >= 0) {
        vh = *(const uint4*)(g_h_hi + (size_t)t * DIM + c);
        vl = *(const uint4*)(g_h_lo + (size_t)t * DIM + c);
    }
    *(uint4*)(g_ag_hi + (size_t)p * DIM + c) = vh;
    *(uint4*)(g_ag_lo + (size_t)p * DIM + c) = vl;
}

__global__ __launch_bounds__(256) void combine_kernel(float* __restrict__ out, int accumulate)
{
    int idx = blockIdx.x * 256 + threadIdx.x;
    if (idx >= N_TOK * (DIM/4)) return;
    int t = idx >> 7, d = (idx & 127) << 2;
    float4 acc;
    if (accumulate) acc = *(float4*)(out + (size_t)t * DIM + d);
    else            acc = make_float4(0.f, 0.f, 0.f, 0.f);
#pragma unroll
    for (int s = 0; s < TOPK; s++) {
        int p = g_pairpos[t*TOPK + s];
        float4 v = *(const float4*)(g_slot + (size_t)p * DIM + d);
        acc.x += v.x; acc.y += v.y; acc.z += v.z; acc.w += v.w;
    }
    *(float4*)(out + (size_t)t * DIM + d) = acc;
}

// ---------------- host -----------------------------------------------------
#define STG_OF(BM, BN)  (2 * (BM) * 80 + 32 * ((BN) * 2 + 16))

extern "C" void kernel_launch(void* const* d_in, const int* in_sizes, int n_in,
                              void* d_out, int out_size)
{
    const float* view[2]  = {(const float*)d_in[0], (const float*)d_in[1]};
    const float* proj_w   = (const float*)d_in[2];
    const float* proj_b   = (const float*)d_in[3];
    const float* router_w = (const float*)d_in[4];
    const float* keys     = (const float*)d_in[5];
    const float* w1       = (const float*)d_in[6];
    const float* b1       = (const float*)d_in[7];
    const float* w2       = (const float*)d_in[8];
    const float* b2       = (const float*)d_in[9];
    float* out = (float*)d_out;

    void *xhi,*xlo,*hhi,*hlo,*aghi,*aglo,*hidhi,*hidlo;
    void *pw,*rw,*w1p,*w2p;
    cudaGetSymbolAddress(&xhi, g_x_hi);     cudaGetSymbolAddress(&xlo, g_x_lo);
    cudaGetSymbolAddress(&hhi, g_h_hi);     cudaGetSymbolAddress(&hlo, g_h_lo);
    cudaGetSymbolAddress(&aghi, g_ag_hi);   cudaGetSymbolAddress(&aglo, g_ag_lo);
    cudaGetSymbolAddress(&hidhi, g_hid_hi); cudaGetSymbolAddress(&hidlo, g_hid_lo);
    cudaGetSymbolAddress(&pw, g_pw);        cudaGetSymbolAddress(&rw, g_rw);
    cudaGetSymbolAddress(&w1p, g_w1);       cudaGetSymbolAddress(&w2p, g_w2);

    constexpr int SM_PR = 3 * STG_OF(128, 256);   // 112128
    constexpr int SM_F1 = 3 * STG_OF(256, 128);   // 148992
    cudaFuncSetAttribute((const void*)mma_gemm_kernel<0,512,512,128,256>,
                         cudaFuncAttributeMaxDynamicSharedMemorySize, SM_PR);
    cudaFuncSetAttribute((const void*)mma_gemm_kernel<1,512,512,128,256>,
                         cudaFuncAttributeMaxDynamicSharedMemorySize, SM_PR);
    cudaFuncSetAttribute((const void*)mma_gemm_kernel<2,512,2048,256,128>,
                         cudaFuncAttributeMaxDynamicSharedMemorySize, SM_F1);
    cudaFuncSetAttribute((const void*)mma_gemm_kernel<3,2048,512,128,256>,
                         cudaFuncAttributeMaxDynamicSharedMemorySize, SM_PR);

    conv8_kernel<<<(2*DIM*DIM/8+255)/256, 256>>>(proj_w,   (__half*)pw,  2*DIM*DIM);
    conv8_kernel<<<(2*DIM*DIM/8+255)/256, 256>>>(router_w, (__half*)rw,  2*DIM*DIM);
    conv8_kernel<<<(N_EXP*DIM*HID/8+255)/256, 256>>>(w1,   (__half*)w1p, N_EXP*DIM*HID);
    conv8_kernel<<<(N_EXP*HID*DIM/8+255)/256, 256>>>(w2,   (__half*)w2p, N_EXP*HID*DIM);

    dim3 gpr(DIM/256, N_TOK/128);        // (2, 32)
    dim3 gf1(HID/128, MAX_T256);         // (16, 80)
    dim3 gf2(DIM/256, MAX_T128);         // (2, 160)

    for (int v = 0; v < 2; v++) {
        split8_kernel<<<(N_TOK*DIM/8+255)/256, 256>>>(view[v],
            (__half*)xhi, (__half*)xlo, N_TOK*DIM);
        mma_gemm_kernel<0,512,512,128,256><<<gpr, 256, SM_PR>>>(
            (const __half*)xhi, (const __half*)xlo, (const __half*)pw, proj_b, v);
        mma_gemm_kernel<1,512,512,128,256><<<gpr, 256, SM_PR>>>(
            (const __half*)hhi, (const __half*)hlo, (const __half*)rw, nullptr, v);
        reset_kernel<<<(PAIR_CAP+255)/256, 256>>>();
        gate_kernel<<<N_TOK, 128>>>(keys);
        scan_kernel<<<1, 1>>>();
        scatter_kernel<<<N_TOK/128, 128>>>();
        gather_kernel<<<(PAIR_CAP*(DIM/8)+255)/256, 256>>>();
        mma_gemm_kernel<2,512,2048,256,128><<<gf1, 256, SM_F1>>>(
            (const __half*)aghi, (const __half*)aglo, (const __half*)w1p, b1, 0);
        mma_gemm_kernel<3,2048,512,128,256><<<gf2, 256, SM_PR>>>(
            (const __half*)hidhi, (const __half*)hidlo, (const __half*)w2p, b2, 0);
        combine_kernel<<<(N_TOK*(DIM/4)+255)/256, 256>>>(out, v);
    }
}